// round 1
// baseline (speedup 1.0000x reference)
#include <cuda_runtime.h>
#include <cuda_bf16.h>
#include <cstdint>

#define T_TOK 4096
#define DIM   2048
#define FFN_  5632
#define NE    8

// ---------------- device scratch (no allocations allowed) ----------------
__device__ int   g_counts[NE];
__device__ int   g_bases[NE];
__device__ int   g_lists[NE * T_TOK];
__device__ float g_wts[NE * T_TOK];
// h buffer: 8192 pair-rows x 5632, fp32 (~176MB)
__device__ float g_h[(size_t)2 * T_TOK * FFN_];

// ---------------- helpers ----------------
__device__ __forceinline__ float to_tf32(float x) {
    float r;
    asm("cvt.rna.tf32.f32 %0, %1;" : "=f"(r) : "f"(x));
    return r;
}

__device__ __forceinline__ void mma8(float* c, const uint32_t* a, const uint32_t* b) {
    asm volatile(
        "mma.sync.aligned.m16n8k8.row.col.f32.tf32.tf32.f32 "
        "{%0,%1,%2,%3}, {%4,%5,%6,%7}, {%8,%9}, {%0,%1,%2,%3};\n"
        : "+f"(c[0]), "+f"(c[1]), "+f"(c[2]), "+f"(c[3])
        : "r"(a[0]), "r"(a[1]), "r"(a[2]), "r"(a[3]),
          "r"(b[0]), "r"(b[1]));
}

// ---------------- kernel 0: zero routing counts ----------------
__global__ void zero_counts_kernel() {
    if (threadIdx.x < NE) g_counts[threadIdx.x] = 0;
}

// ---------------- kernel 1: router (one warp per token) ----------------
__global__ void router_kernel(const float* __restrict__ x, const float* __restrict__ gw) {
    int warp = threadIdx.x >> 5;
    int lane = threadIdx.x & 31;
    int t = blockIdx.x * 8 + warp;
    if (t >= T_TOK) return;
    const float* xt = x + (size_t)t * DIM;

    float s[NE];
#pragma unroll
    for (int e = 0; e < NE; e++) s[e] = 0.f;
    for (int d = lane; d < DIM; d += 32) {
        float xv = xt[d];
#pragma unroll
        for (int e = 0; e < NE; e++) s[e] += xv * gw[e * DIM + d];
    }
#pragma unroll
    for (int e = 0; e < NE; e++) {
#pragma unroll
        for (int o = 16; o > 0; o >>= 1) s[e] += __shfl_xor_sync(0xffffffffu, s[e], o);
    }
    if (lane == 0) {
        int i0 = 0; float v0 = s[0];
#pragma unroll
        for (int e = 1; e < NE; e++) if (s[e] > v0) { v0 = s[e]; i0 = e; }
        int i1 = -1; float v1 = -1e30f;
#pragma unroll
        for (int e = 0; e < NE; e++) if (e != i0 && s[e] > v1) { v1 = s[e]; i1 = e; }
        // softmax over [v0, v1], v0 >= v1
        float e1 = __expf(v1 - v0);
        float w0 = 1.f / (1.f + e1);
        float w1 = e1 * w0;
        int p0 = atomicAdd(&g_counts[i0], 1);
        g_lists[i0 * T_TOK + p0] = t;
        g_wts[i0 * T_TOK + p0] = w0;
        int p1 = atomicAdd(&g_counts[i1], 1);
        g_lists[i1 * T_TOK + p1] = t;
        g_wts[i1 * T_TOK + p1] = w1;
    }
}

// ---------------- kernel 2: prefix-sum bases ----------------
__global__ void prefix_kernel() {
    if (threadIdx.x == 0) {
        int s = 0;
#pragma unroll
        for (int e = 0; e < NE; e++) { g_bases[e] = s; s += g_counts[e]; }
    }
}

// ---------------- kernel 3: out = bias ----------------
__global__ void init_out_kernel(float* __restrict__ out, const float* __restrict__ bias) {
    int i = blockIdx.x * 256 + threadIdx.x;
    out[i] = bias[i & (DIM - 1)];
}

// ---------------- kernel 4: gate/up GEMM + SiLU  (tf32 mma) ----------------
// Block tile: 128(M tokens) x 128(N ffn), KC=16. 256 threads = 8 warps (2x4),
// warp tile 64x32 -> 4x4 mma tiles of 16x8, dual accumulators (gate & up).
__global__ __launch_bounds__(256, 1) void gemm1_kernel(
    const float* __restrict__ x, const float* __restrict__ wg, const float* __restrict__ wu)
{
    const int e  = blockIdx.z;
    const int m0 = blockIdx.y * 128;
    const int count = g_counts[e];
    if (m0 >= count) return;
    const int ft = blockIdx.x;
    const int base = g_bases[e];

    __shared__ float sA [128 * 20];
    __shared__ float sBg[128 * 20];
    __shared__ float sBu[128 * 20];

    const int tid  = threadIdx.x;
    const int row0 = tid >> 2;            // 0..63
    const int kq   = (tid & 3) << 2;      // 0,4,8,12
    const int row1 = row0 + 64;

    const float* ap0 = nullptr;
    const float* ap1 = nullptr;
    if (m0 + row0 < count) ap0 = x + (size_t)g_lists[e * T_TOK + m0 + row0] * DIM + kq;
    if (m0 + row1 < count) ap1 = x + (size_t)g_lists[e * T_TOK + m0 + row1] * DIM + kq;
    const size_t wb = (size_t)e * FFN_ * DIM;
    const float* bg0 = wg + wb + (size_t)(ft * 128 + row0) * DIM + kq;
    const float* bg1 = wg + wb + (size_t)(ft * 128 + row1) * DIM + kq;
    const float* bu0 = wu + wb + (size_t)(ft * 128 + row0) * DIM + kq;
    const float* bu1 = wu + wb + (size_t)(ft * 128 + row1) * DIM + kq;

    float accg[4][4][4], accu[4][4][4];
#pragma unroll
    for (int i = 0; i < 4; i++)
#pragma unroll
        for (int j = 0; j < 4; j++)
#pragma unroll
            for (int k = 0; k < 4; k++) { accg[i][j][k] = 0.f; accu[i][j][k] = 0.f; }

    const int warp = tid >> 5, lane = tid & 31;
    const int wm = (warp >> 2) * 64, wn = (warp & 3) * 32;
    const int grp = lane >> 2, tig = lane & 3;

    const float4 z4 = make_float4(0.f, 0.f, 0.f, 0.f);
    float4 ra0 = ap0 ? *(const float4*)(ap0) : z4;
    float4 ra1 = ap1 ? *(const float4*)(ap1) : z4;
    float4 rg0 = *(const float4*)(bg0);
    float4 rg1 = *(const float4*)(bg1);
    float4 ru0 = *(const float4*)(bu0);
    float4 ru1 = *(const float4*)(bu1);

    for (int kk = 0; kk < DIM; kk += 16) {
        {   // stage regs -> smem (rounded to tf32 once, here)
            float* p;
            p = sA  + row0 * 20 + kq; p[0]=to_tf32(ra0.x); p[1]=to_tf32(ra0.y); p[2]=to_tf32(ra0.z); p[3]=to_tf32(ra0.w);
            p = sA  + row1 * 20 + kq; p[0]=to_tf32(ra1.x); p[1]=to_tf32(ra1.y); p[2]=to_tf32(ra1.z); p[3]=to_tf32(ra1.w);
            p = sBg + row0 * 20 + kq; p[0]=to_tf32(rg0.x); p[1]=to_tf32(rg0.y); p[2]=to_tf32(rg0.z); p[3]=to_tf32(rg0.w);
            p = sBg + row1 * 20 + kq; p[0]=to_tf32(rg1.x); p[1]=to_tf32(rg1.y); p[2]=to_tf32(rg1.z); p[3]=to_tf32(rg1.w);
            p = sBu + row0 * 20 + kq; p[0]=to_tf32(ru0.x); p[1]=to_tf32(ru0.y); p[2]=to_tf32(ru0.z); p[3]=to_tf32(ru0.w);
            p = sBu + row1 * 20 + kq; p[0]=to_tf32(ru1.x); p[1]=to_tf32(ru1.y); p[2]=to_tf32(ru1.z); p[3]=to_tf32(ru1.w);
        }
        __syncthreads();
        if (kk + 16 < DIM) {  // prefetch next K-slab while computing this one
            int ko = kk + 16;
            ra0 = ap0 ? *(const float4*)(ap0 + ko) : z4;
            ra1 = ap1 ? *(const float4*)(ap1 + ko) : z4;
            rg0 = *(const float4*)(bg0 + ko);
            rg1 = *(const float4*)(bg1 + ko);
            ru0 = *(const float4*)(bu0 + ko);
            ru1 = *(const float4*)(bu1 + ko);
        }
#pragma unroll
        for (int ks = 0; ks < 16; ks += 8) {
            uint32_t af[4][4];
#pragma unroll
            for (int im = 0; im < 4; im++) {
                int r = wm + im * 16 + grp;
                af[im][0] = __float_as_uint(sA[r * 20 + ks + tig]);
                af[im][1] = __float_as_uint(sA[(r + 8) * 20 + ks + tig]);
                af[im][2] = __float_as_uint(sA[r * 20 + ks + tig + 4]);
                af[im][3] = __float_as_uint(sA[(r + 8) * 20 + ks + tig + 4]);
            }
#pragma unroll
            for (int jn = 0; jn < 4; jn++) {
                int c = wn + jn * 8 + grp;
                uint32_t bg[2], bu[2];
                bg[0] = __float_as_uint(sBg[c * 20 + ks + tig]);
                bg[1] = __float_as_uint(sBg[c * 20 + ks + tig + 4]);
                bu[0] = __float_as_uint(sBu[c * 20 + ks + tig]);
                bu[1] = __float_as_uint(sBu[c * 20 + ks + tig + 4]);
#pragma unroll
                for (int im = 0; im < 4; im++) {
                    mma8(accg[im][jn], af[im], bg);
                    mma8(accu[im][jn], af[im], bu);
                }
            }
        }
        __syncthreads();
    }

    // epilogue: h = silu(g) * u  -> scatter to per-pair rows of g_h
#pragma unroll
    for (int im = 0; im < 4; im++) {
        int rA  = wm + im * 16 + grp;
        int mmA = m0 + rA;
        int mmB = mmA + 8;
        bool okA = mmA < count, okB = mmB < count;
        size_t hrA = (size_t)(base + mmA) * FFN_;
        size_t hrB = (size_t)(base + mmB) * FFN_;
#pragma unroll
        for (int jn = 0; jn < 4; jn++) {
            int col = ft * 128 + wn + jn * 8 + tig * 2;
            if (okA) {
                float g0 = accg[im][jn][0], g1 = accg[im][jn][1];
                float h0 = (g0 / (1.f + __expf(-g0))) * accu[im][jn][0];
                float h1 = (g1 / (1.f + __expf(-g1))) * accu[im][jn][1];
                *(float2*)(g_h + hrA + col) = make_float2(h0, h1);
            }
            if (okB) {
                float g2 = accg[im][jn][2], g3 = accg[im][jn][3];
                float h2 = (g2 / (1.f + __expf(-g2))) * accu[im][jn][2];
                float h3 = (g3 / (1.f + __expf(-g3))) * accu[im][jn][3];
                *(float2*)(g_h + hrB + col) = make_float2(h2, h3);
            }
        }
    }
}

// ---------------- kernel 5: down-proj GEMM + weighted combine ----------------
__global__ __launch_bounds__(256, 1) void gemm2_kernel(
    const float* __restrict__ wo, float* __restrict__ out)
{
    const int e  = blockIdx.z;
    const int m0 = blockIdx.y * 128;
    const int count = g_counts[e];
    if (m0 >= count) return;
    const int dt = blockIdx.x;
    const int base = g_bases[e];

    __shared__ float sA[128 * 20];
    __shared__ float sB[128 * 20];

    const int tid  = threadIdx.x;
    const int row0 = tid >> 2;
    const int kq   = (tid & 3) << 2;
    const int row1 = row0 + 64;

    const float* ap0 = (m0 + row0 < count) ? g_h + (size_t)(base + m0 + row0) * FFN_ + kq : nullptr;
    const float* ap1 = (m0 + row1 < count) ? g_h + (size_t)(base + m0 + row1) * FFN_ + kq : nullptr;
    const size_t wb = (size_t)e * DIM * FFN_;
    const float* bp0 = wo + wb + (size_t)(dt * 128 + row0) * FFN_ + kq;
    const float* bp1 = wo + wb + (size_t)(dt * 128 + row1) * FFN_ + kq;

    float acc[4][4][4];
#pragma unroll
    for (int i = 0; i < 4; i++)
#pragma unroll
        for (int j = 0; j < 4; j++)
#pragma unroll
            for (int k = 0; k < 4; k++) acc[i][j][k] = 0.f;

    const int warp = tid >> 5, lane = tid & 31;
    const int wm = (warp >> 2) * 64, wn = (warp & 3) * 32;
    const int grp = lane >> 2, tig = lane & 3;

    const float4 z4 = make_float4(0.f, 0.f, 0.f, 0.f);
    float4 ra0 = ap0 ? *(const float4*)(ap0) : z4;
    float4 ra1 = ap1 ? *(const float4*)(ap1) : z4;
    float4 rb0 = *(const float4*)(bp0);
    float4 rb1 = *(const float4*)(bp1);

    for (int kk = 0; kk < FFN_; kk += 16) {
        {
            float* p;
            p = sA + row0 * 20 + kq; p[0]=to_tf32(ra0.x); p[1]=to_tf32(ra0.y); p[2]=to_tf32(ra0.z); p[3]=to_tf32(ra0.w);
            p = sA + row1 * 20 + kq; p[0]=to_tf32(ra1.x); p[1]=to_tf32(ra1.y); p[2]=to_tf32(ra1.z); p[3]=to_tf32(ra1.w);
            p = sB + row0 * 20 + kq; p[0]=to_tf32(rb0.x); p[1]=to_tf32(rb0.y); p[2]=to_tf32(rb0.z); p[3]=to_tf32(rb0.w);
            p = sB + row1 * 20 + kq; p[0]=to_tf32(rb1.x); p[1]=to_tf32(rb1.y); p[2]=to_tf32(rb1.z); p[3]=to_tf32(rb1.w);
        }
        __syncthreads();
        if (kk + 16 < FFN_) {
            int ko = kk + 16;
            ra0 = ap0 ? *(const float4*)(ap0 + ko) : z4;
            ra1 = ap1 ? *(const float4*)(ap1 + ko) : z4;
            rb0 = *(const float4*)(bp0 + ko);
            rb1 = *(const float4*)(bp1 + ko);
        }
#pragma unroll
        for (int ks = 0; ks < 16; ks += 8) {
            uint32_t af[4][4];
#pragma unroll
            for (int im = 0; im < 4; im++) {
                int r = wm + im * 16 + grp;
                af[im][0] = __float_as_uint(sA[r * 20 + ks + tig]);
                af[im][1] = __float_as_uint(sA[(r + 8) * 20 + ks + tig]);
                af[im][2] = __float_as_uint(sA[r * 20 + ks + tig + 4]);
                af[im][3] = __float_as_uint(sA[(r + 8) * 20 + ks + tig + 4]);
            }
#pragma unroll
            for (int jn = 0; jn < 4; jn++) {
                int c = wn + jn * 8 + grp;
                uint32_t bf[2];
                bf[0] = __float_as_uint(sB[c * 20 + ks + tig]);
                bf[1] = __float_as_uint(sB[c * 20 + ks + tig + 4]);
#pragma unroll
                for (int im = 0; im < 4; im++) mma8(acc[im][jn], af[im], bf);
            }
        }
        __syncthreads();
    }

    // epilogue: out[token, d] += w * y  (out pre-initialized with bias)
#pragma unroll
    for (int im = 0; im < 4; im++) {
        int rA  = wm + im * 16 + grp;
        int mmA = m0 + rA;
        int mmB = mmA + 8;
        bool okA = mmA < count, okB = mmB < count;
        int   tokA = 0, tokB = 0;
        float wA = 0.f, wB = 0.f;
        if (okA) { tokA = g_lists[e * T_TOK + mmA]; wA = g_wts[e * T_TOK + mmA]; }
        if (okB) { tokB = g_lists[e * T_TOK + mmB]; wB = g_wts[e * T_TOK + mmB]; }
#pragma unroll
        for (int jn = 0; jn < 4; jn++) {
            int col = dt * 128 + wn + jn * 8 + tig * 2;
            if (okA) {
                float* o = out + (size_t)tokA * DIM + col;
                atomicAdd(o,     wA * acc[im][jn][0]);
                atomicAdd(o + 1, wA * acc[im][jn][1]);
            }
            if (okB) {
                float* o = out + (size_t)tokB * DIM + col;
                atomicAdd(o,     wB * acc[im][jn][2]);
                atomicAdd(o + 1, wB * acc[im][jn][3]);
            }
        }
    }
}

// ---------------- launch ----------------
extern "C" void kernel_launch(void* const* d_in, const int* in_sizes, int n_in,
                              void* d_out, int out_size) {
    const float* x       = (const float*)d_in[0];  // [2,2048,2048]
    const float* gate_w  = (const float*)d_in[1];  // [8,2048]
    const float* w_gate  = (const float*)d_in[2];  // [8,5632,2048]
    const float* w_up    = (const float*)d_in[3];  // [8,5632,2048]
    const float* w_out   = (const float*)d_in[4];  // [8,2048,5632]
    const float* bias    = (const float*)d_in[5];  // [2048]
    float* out = (float*)d_out;                    // [2,2048,2048]

    zero_counts_kernel<<<1, 32>>>();
    router_kernel<<<T_TOK / 8, 256>>>(x, gate_w);
    prefix_kernel<<<1, 32>>>();
    init_out_kernel<<<(T_TOK * DIM) / 256, 256>>>(out, bias);
    gemm1_kernel<<<dim3(FFN_ / 128, T_TOK / 128, NE), 256>>>(x, w_gate, w_up);
    gemm2_kernel<<<dim3(DIM / 128, T_TOK / 128, NE), 256>>>(w_out, out);
}